// round 3
// baseline (speedup 1.0000x reference)
#include <cuda_runtime.h>
#include <cstdint>

// ---------------------------------------------------------------------------
// RowLSTM: x(16,64,64,64), Wi(512,64,1,3), bi(512), Wh(512,128), bh(512)
// out: (16,128,64,64) fp32
// ---------------------------------------------------------------------------

#define B_  16
#define C_  64
#define H_  64
#define W_  64
#define HID_ 128
#define G_  512   // 4*HID
#define K_  192   // C_*3

static __device__ float g_i2h[(size_t)H_ * B_ * W_ * G_];   // 134 MB [h][b][w][g]
static __device__ float g_WiT[(size_t)K_ * G_];             // 393 KB [k][g]

// ---- f32x2 helpers ---------------------------------------------------------
__device__ __forceinline__ uint64_t pk2(float a, float b) {
    uint64_t r; asm("mov.b64 %0,{%1,%2};" : "=l"(r) : "f"(a), "f"(b)); return r;
}
__device__ __forceinline__ void upk2(uint64_t v, float& a, float& b) {
    asm("mov.b64 {%0,%1},%2;" : "=f"(a), "=f"(b) : "l"(v));
}
__device__ __forceinline__ uint64_t ffma2(uint64_t a, uint64_t b, uint64_t c) {
    uint64_t d; asm("fma.rn.f32x2 %0,%1,%2,%3;" : "=l"(d) : "l"(a), "l"(b), "l"(c)); return d;
}

// ---------------------------------------------------------------------------
// Kernel 0: transpose Wi -> WiT[k][g]
// ---------------------------------------------------------------------------
__global__ void prep_kernel(const float* __restrict__ Wi)
{
    int k = blockIdx.x;
    int g = threadIdx.x;
    g_WiT[(size_t)k * G_ + g] = Wi[(size_t)g * K_ + k];
}

// ---------------------------------------------------------------------------
// Kernel A: i2h GEMM. Grid 2048 = (b, h, gate-half). 256 threads.
// thread: 8 gates (g0l=(tid&31)*8 within 256-gate half), 8 cols (w0=(tid>>5)*8)
// ---------------------------------------------------------------------------
__global__ void __launch_bounds__(256, 2)
i2h_kernel(const float* __restrict__ x,
           const float* __restrict__ bi, const float* __restrict__ bh)
{
    const int b  = blockIdx.x & 15;
    const int h  = (blockIdx.x >> 4) & 63;
    const int gh = blockIdx.x >> 10;        // 0/1 gate half
    const int tid = threadIdx.x;

    __shared__ float xs[C_][68];         // [c][w+1], zero pad ends
    __shared__ float ws[2][12][256];     // ping-pong Wi chunks [kk][g-local]

    for (int idx = tid; idx < C_ * W_; idx += 256) {
        int c = idx >> 6, w = idx & 63;
        xs[c][w + 1] = x[((((size_t)b * C_) + c) * H_ + h) * W_ + w];
    }
    if (tid < C_) { xs[tid][0] = 0.f; xs[tid][65] = 0.f; xs[tid][66] = 0.f; xs[tid][67] = 0.f; }

    const int gbase = gh * 256;
    float r[12];
#pragma unroll
    for (int j = 0; j < 12; j++) r[j] = g_WiT[(size_t)j * G_ + gbase + tid];
#pragma unroll
    for (int j = 0; j < 12; j++) ws[0][j][tid] = r[j];
    __syncthreads();

    const int g0l = (tid & 31) * 8;   // local gate base within the 256-half
    const int w0  = (tid >> 5) * 8;

    uint64_t acc2[4][8];
#pragma unroll
    for (int i = 0; i < 4; i++)
#pragma unroll
        for (int j = 0; j < 8; j++) acc2[i][j] = 0ull;

    for (int kc = 0; kc < 16; kc++) {
        if (kc < 15) {
#pragma unroll
            for (int j = 0; j < 12; j++)
                r[j] = g_WiT[((size_t)(kc + 1) * 12 + j) * G_ + gbase + tid];
        }
        const int buf = kc & 1;

#pragma unroll
        for (int cc = 0; cc < 4; cc++) {
            const int c = kc * 4 + cc;
            const float* xrow = &xs[c][w0];
            float4 xa = *reinterpret_cast<const float4*>(xrow);
            float4 xb = *reinterpret_cast<const float4*>(xrow + 4);
            float4 xc = *reinterpret_cast<const float4*>(xrow + 8);
            float xr[12] = {xa.x, xa.y, xa.z, xa.w,
                            xb.x, xb.y, xb.z, xb.w,
                            xc.x, xc.y, xc.z, xc.w};
            uint64_t xbp[10];
#pragma unroll
            for (int o = 0; o < 10; o++) xbp[o] = pk2(xr[o], xr[o]);

#pragma unroll
            for (int kw = 0; kw < 3; kw++) {
                const int kk = cc * 3 + kw;
                // adjacent gates contiguous in smem -> direct u64 pairs, no packing
                const uint64_t* wrow = reinterpret_cast<const uint64_t*>(&ws[buf][kk][g0l]);
                uint64_t wp0 = wrow[0], wp1 = wrow[1], wp2 = wrow[2], wp3 = wrow[3];
#pragma unroll
                for (int j = 0; j < 8; j++) {
                    acc2[0][j] = ffma2(wp0, xbp[j + kw], acc2[0][j]);
                    acc2[1][j] = ffma2(wp1, xbp[j + kw], acc2[1][j]);
                    acc2[2][j] = ffma2(wp2, xbp[j + kw], acc2[2][j]);
                    acc2[3][j] = ffma2(wp3, xbp[j + kw], acc2[3][j]);
                }
            }
        }

        if (kc < 15) {
            const int nb = (kc + 1) & 1;
#pragma unroll
            for (int j = 0; j < 12; j++) ws[nb][j][tid] = r[j];
        }
        __syncthreads();
    }

    const int g0 = gbase + g0l;     // global gate base
    float bias[8];
#pragma unroll
    for (int i = 0; i < 8; i++) bias[i] = bi[g0 + i] + bh[g0 + i];

    const size_t obase = ((((size_t)h * B_ + b) * W_) + w0) * G_ + g0;
#pragma unroll
    for (int j = 0; j < 8; j++) {
        float o0, o1, o2, o3, o4, o5, o6, o7;
        upk2(acc2[0][j], o0, o1);
        upk2(acc2[1][j], o2, o3);
        upk2(acc2[2][j], o4, o5);
        upk2(acc2[3][j], o6, o7);
        float4 v0 = make_float4(o0 + bias[0], o1 + bias[1], o2 + bias[2], o3 + bias[3]);
        float4 v1 = make_float4(o4 + bias[4], o5 + bias[5], o6 + bias[6], o7 + bias[7]);
        *reinterpret_cast<float4*>(&g_i2h[obase + (size_t)j * G_])     = v0;
        *reinterpret_cast<float4*>(&g_i2h[obase + (size_t)j * G_ + 4]) = v1;
    }
}

// ---------------------------------------------------------------------------
// Kernel B: recurrent scan. 256 blocks = (b, w-group of 4 cols), 512 threads.
// thread t owns gate row t.
// ---------------------------------------------------------------------------
__device__ __forceinline__ float sigmf(float v) {
    return __fdividef(1.0f, 1.0f + __expf(-v));
}
__device__ __forceinline__ float tanhf_(float v) {
    return __fdividef(2.0f, 1.0f + __expf(-2.0f * v)) - 1.0f;
}

__global__ void __launch_bounds__(512, 2)
rec_kernel(const float* __restrict__ Wh, float* __restrict__ out)
{
    const int b  = blockIdx.x >> 4;
    const int w0 = (blockIdx.x & 15) * 4;
    const int t  = threadIdx.x;

    __shared__ float hbuf[HID_][4];   // [d][col]
    __shared__ float cbuf[HID_][4];
    __shared__ float gbuf[4][G_];     // [col][gate]

    if (t < HID_ * 4 / 4) {           // 512 >= 128; each thread inits 1 d across 4 cols
        // init 4-col rows: t<128 handles d=t
    }
    for (int p = t; p < HID_ * 4; p += 512) {
        (&hbuf[0][0])[p] = 0.f;
        (&cbuf[0][0])[p] = 0.f;
    }
    __syncthreads();

    const float4* __restrict__ Wh4 = reinterpret_cast<const float4*>(Wh) + (size_t)t * 32;

    for (int row = 0; row < H_; row++) {
        const float* gp = g_i2h + ((((size_t)row * B_ + b) * W_) + w0) * G_ + t;
        float gv[4];
#pragma unroll
        for (int col = 0; col < 4; col++) gv[col] = __ldg(gp + (size_t)col * G_);

        uint64_t accp[2] = {0ull, 0ull};   // col pairs (0,1)(2,3)

#pragma unroll 4
        for (int d4 = 0; d4 < 32; d4++) {
            float4 wv = __ldg(Wh4 + d4);
#pragma unroll
            for (int e = 0; e < 4; e++) {
                const float w = (e == 0) ? wv.x : (e == 1) ? wv.y : (e == 2) ? wv.z : wv.w;
                const uint64_t wp = pk2(w, w);
                const uint64_t* hp = reinterpret_cast<const uint64_t*>(&hbuf[d4 * 4 + e][0]);
                accp[0] = ffma2(wp, hp[0], accp[0]);
                accp[1] = ffma2(wp, hp[1], accp[1]);
            }
        }

#pragma unroll
        for (int q = 0; q < 2; q++) {
            float lo, hi;
            upk2(accp[q], lo, hi);
            gbuf[2 * q][t]     = lo + gv[2 * q];
            gbuf[2 * q + 1][t] = hi + gv[2 * q + 1];
        }
        __syncthreads();

        // pointwise: 512 (col,d) pairs, exactly 1 per thread
        {
            int col = t >> 7;
            int d   = t & 127;
            float ig = gbuf[col][d];
            float fg = gbuf[col][HID_ + d];
            float og = gbuf[col][2 * HID_ + d];
            float gg = gbuf[col][3 * HID_ + d];
            float cv = sigmf(fg) * cbuf[d][col] + sigmf(ig) * tanhf_(gg);
            float hv = sigmf(og) * tanhf_(cv);
            cbuf[d][col] = cv;
            hbuf[d][col] = hv;
        }
        __syncthreads();

        // output: out[b][d][row][w0..w0+4)
        if (t < HID_) {
            const int d = t;
            float4 v = make_float4(hbuf[d][0], hbuf[d][1], hbuf[d][2], hbuf[d][3]);
            float* op = out + ((((size_t)b * HID_ + d) * H_) + row) * W_ + w0;
            *reinterpret_cast<float4*>(op) = v;
        }
    }
}

// ---------------------------------------------------------------------------
extern "C" void kernel_launch(void* const* d_in, const int* in_sizes, int n_in,
                              void* d_out, int out_size)
{
    (void)in_sizes; (void)n_in; (void)out_size;
    const float* x  = (const float*)d_in[0];
    const float* Wi = (const float*)d_in[1];
    const float* bi = (const float*)d_in[2];
    const float* Wh = (const float*)d_in[3];
    const float* bh = (const float*)d_in[4];
    float* out = (float*)d_out;

    prep_kernel<<<K_, G_>>>(Wi);
    i2h_kernel<<<B_ * H_ * 2, 256>>>(x, bi, bh);
    rec_kernel<<<B_ * (W_ / 4), 512>>>(Wh, out);
}

// round 4
// speedup vs baseline: 1.8867x; 1.8867x over previous
#include <cuda_runtime.h>
#include <cstdint>

// ---------------------------------------------------------------------------
// RowLSTM: x(16,64,64,64), Wi(512,64,1,3), bi(512), Wh(512,128), bh(512)
// out: (16,128,64,64) fp32
// ---------------------------------------------------------------------------

#define B_  16
#define C_  64
#define H_  64
#define W_  64
#define HID_ 128
#define G_  512   // 4*HID
#define K_  192   // C_*3

static __device__ float g_i2h[(size_t)H_ * B_ * W_ * G_];   // 134 MB [h][b][w][g]
static __device__ float g_WiT[(size_t)K_ * G_];             // [k][g]
static __device__ float g_WhT[(size_t)HID_ * G_];           // [k][g]

__device__ __forceinline__ float sigmf(float v) {
    return __fdividef(1.0f, 1.0f + __expf(-v));
}
__device__ __forceinline__ float tanhf_(float v) {
    return __fdividef(2.0f, 1.0f + __expf(-2.0f * v)) - 1.0f;
}

// ---------------------------------------------------------------------------
// Kernel 0: transpose Wi -> WiT[k][g], Wh -> WhT[k][g]
// ---------------------------------------------------------------------------
__global__ void prep_kernel(const float* __restrict__ Wi, const float* __restrict__ Wh)
{
    int g = threadIdx.x;
    if (blockIdx.x < K_) {
        int k = blockIdx.x;
        g_WiT[(size_t)k * G_ + g] = Wi[(size_t)g * K_ + k];
    } else {
        int k = blockIdx.x - K_;
        g_WhT[(size_t)k * G_ + g] = Wh[(size_t)g * HID_ + k];
    }
}

// ---------------------------------------------------------------------------
// Kernel A: i2h GEMM. Grid 2048 = (b, h, gate-half). 512 threads.
// thread: 4 gates (g0l=(tid&63)*4 within 256-gate half), 8 cols (w0=(tid>>6)*8)
// ---------------------------------------------------------------------------
__global__ void __launch_bounds__(512, 2)
i2h_kernel(const float* __restrict__ x,
           const float* __restrict__ bi, const float* __restrict__ bh)
{
    const int b  = blockIdx.x & 15;
    const int h  = (blockIdx.x >> 4) & 63;
    const int gh = blockIdx.x >> 10;        // 0/1 gate half
    const int tid = threadIdx.x;
    const int gbase = gh * 256;

    __shared__ float xs[C_][68];       // [c][w+1], zero pad ends
    __shared__ float ws[12][256];      // Wi chunk [kk][g-local]

    for (int idx = tid; idx < C_ * W_; idx += 512) {
        int c = idx >> 6, w = idx & 63;
        xs[c][w + 1] = x[((((size_t)b * C_) + c) * H_ + h) * W_ + w];
    }
    if (tid < C_) { xs[tid][0] = 0.f; xs[tid][65] = 0.f; xs[tid][66] = 0.f; xs[tid][67] = 0.f; }

    const int g0l = (tid & 63) * 4;    // local gate base (4 gates)
    const int w0  = (tid >> 6) * 8;    // 8 cols

    float acc[4][8];
#pragma unroll
    for (int i = 0; i < 4; i++)
#pragma unroll
        for (int j = 0; j < 8; j++) acc[i][j] = 0.f;

    for (int kc = 0; kc < 16; kc++) {
        __syncthreads();
        // stage chunk: 12*256 = 3072 words by 512 threads, coalesced
#pragma unroll
        for (int u = 0; u < 6; u++) {
            int idx = tid + u * 512;
            int j = idx >> 8, g = idx & 255;
            ws[j][g] = g_WiT[((size_t)kc * 12 + j) * G_ + gbase + g];
        }
        __syncthreads();

#pragma unroll
        for (int cc = 0; cc < 4; cc++) {
            const int c = kc * 4 + cc;
            const float* xrow = &xs[c][w0];
            float4 xa = *reinterpret_cast<const float4*>(xrow);
            float4 xb = *reinterpret_cast<const float4*>(xrow + 4);
            float4 xc = *reinterpret_cast<const float4*>(xrow + 8);
            float xr[12] = {xa.x, xa.y, xa.z, xa.w,
                            xb.x, xb.y, xb.z, xb.w,
                            xc.x, xc.y, xc.z, xc.w};
#pragma unroll
            for (int kw = 0; kw < 3; kw++) {
                float4 wv = *reinterpret_cast<const float4*>(&ws[cc * 3 + kw][g0l]);
                float w0v = wv.x, w1v = wv.y, w2v = wv.z, w3v = wv.w;
#pragma unroll
                for (int j = 0; j < 8; j++) {
                    float xv = xr[j + kw];
                    acc[0][j] = fmaf(w0v, xv, acc[0][j]);
                    acc[1][j] = fmaf(w1v, xv, acc[1][j]);
                    acc[2][j] = fmaf(w2v, xv, acc[2][j]);
                    acc[3][j] = fmaf(w3v, xv, acc[3][j]);
                }
            }
        }
    }

    const int g0 = gbase + g0l;
    float bias[4];
#pragma unroll
    for (int i = 0; i < 4; i++) bias[i] = bi[g0 + i] + bh[g0 + i];

    const size_t obase = ((((size_t)h * B_ + b) * W_) + w0) * G_ + g0;
#pragma unroll
    for (int j = 0; j < 8; j++) {
        float4 v = make_float4(acc[0][j] + bias[0], acc[1][j] + bias[1],
                               acc[2][j] + bias[2], acc[3][j] + bias[3]);
        *reinterpret_cast<float4*>(&g_i2h[obase + (size_t)j * G_]) = v;
    }
}

// ---------------------------------------------------------------------------
// Kernel B: recurrent scan. 128 blocks = (b, w-group of 8 cols), 512 threads.
// thread: gate-quad q = t&127 (gates 4q..4q+3), col-pair ch = t>>7 (cols 2ch,2ch+1)
// WhT loads coalesced (float4 per gate-quad at row k).
// ---------------------------------------------------------------------------
#define HP 10   // hbuf/cbuf row padding (words)

__global__ void __launch_bounds__(512, 1)
rec_kernel(float* __restrict__ out)
{
    const int b  = blockIdx.x >> 3;
    const int w0 = (blockIdx.x & 7) * 8;
    const int t  = threadIdx.x;
    const int q  = t & 127;
    const int ch = t >> 7;          // 0..3

    __shared__ float hbuf[HID_ * HP];   // [k][col] padded rows of HP
    __shared__ float cbuf[HID_ * HP];
    __shared__ float gbuf[8][G_];       // [col][gate]

    for (int p = t; p < HID_ * HP; p += 512) { hbuf[p] = 0.f; cbuf[p] = 0.f; }
    __syncthreads();

    const float4* __restrict__ WhT4 = reinterpret_cast<const float4*>(g_WhT);

    for (int row = 0; row < H_; row++) {
        // i2h gate init: float4 per col (gates 4q..4q+3), coalesced across q
        const size_t ibase = ((((size_t)row * B_ + b) * W_) + w0 + 2 * ch) * G_ + 4 * q;
        float4 gv0 = *reinterpret_cast<const float4*>(&g_i2h[ibase]);
        float4 gv1 = *reinterpret_cast<const float4*>(&g_i2h[ibase + G_]);

        float a00 = 0.f, a10 = 0.f, a20 = 0.f, a30 = 0.f;   // col 2ch
        float a01 = 0.f, a11 = 0.f, a21 = 0.f, a31 = 0.f;   // col 2ch+1

#pragma unroll 4
        for (int k = 0; k < HID_; k++) {
            float4 wv = __ldg(&WhT4[(size_t)k * (G_ / 4) + q]);
            float2 hv = *reinterpret_cast<const float2*>(&hbuf[k * HP + 2 * ch]);
            a00 = fmaf(wv.x, hv.x, a00); a01 = fmaf(wv.x, hv.y, a01);
            a10 = fmaf(wv.y, hv.x, a10); a11 = fmaf(wv.y, hv.y, a11);
            a20 = fmaf(wv.z, hv.x, a20); a21 = fmaf(wv.z, hv.y, a21);
            a30 = fmaf(wv.w, hv.x, a30); a31 = fmaf(wv.w, hv.y, a31);
        }

        *reinterpret_cast<float4*>(&gbuf[2 * ch][4 * q]) =
            make_float4(a00 + gv0.x, a10 + gv0.y, a20 + gv0.z, a30 + gv0.w);
        *reinterpret_cast<float4*>(&gbuf[2 * ch + 1][4 * q]) =
            make_float4(a01 + gv1.x, a11 + gv1.y, a21 + gv1.z, a31 + gv1.w);
        __syncthreads();

        // pointwise: 1024 (col,d) pairs / 512 threads
#pragma unroll
        for (int pp = 0; pp < 2; pp++) {
            int p   = t + pp * 512;
            int col = p >> 7;
            int d   = p & 127;
            float ig = gbuf[col][d];
            float fg = gbuf[col][HID_ + d];
            float og = gbuf[col][2 * HID_ + d];
            float gg = gbuf[col][3 * HID_ + d];
            float cv = sigmf(fg) * cbuf[d * HP + col] + sigmf(ig) * tanhf_(gg);
            float hv = sigmf(og) * tanhf_(cv);
            cbuf[d * HP + col] = cv;
            hbuf[d * HP + col] = hv;
        }
        __syncthreads();

        // output: out[b][d][row][w0..w0+8)
        if (t < HID_) {
            const int d = t;
            float4 v0 = make_float4(hbuf[d * HP + 0], hbuf[d * HP + 1],
                                    hbuf[d * HP + 2], hbuf[d * HP + 3]);
            float4 v1 = make_float4(hbuf[d * HP + 4], hbuf[d * HP + 5],
                                    hbuf[d * HP + 6], hbuf[d * HP + 7]);
            float* op = out + ((((size_t)b * HID_ + d) * H_) + row) * W_ + w0;
            *reinterpret_cast<float4*>(op)     = v0;
            *reinterpret_cast<float4*>(op + 4) = v1;
        }
    }
}

// ---------------------------------------------------------------------------
extern "C" void kernel_launch(void* const* d_in, const int* in_sizes, int n_in,
                              void* d_out, int out_size)
{
    (void)in_sizes; (void)n_in; (void)out_size;
    const float* x  = (const float*)d_in[0];
    const float* Wi = (const float*)d_in[1];
    const float* bi = (const float*)d_in[2];
    const float* Wh = (const float*)d_in[3];
    const float* bh = (const float*)d_in[4];
    float* out = (float*)d_out;

    prep_kernel<<<K_ + HID_, G_>>>(Wi, Wh);
    i2h_kernel<<<B_ * H_ * 2, 512>>>(x, bi, bh);
    rec_kernel<<<B_ * (W_ / 8), 512>>>(out);
}